// round 10
// baseline (speedup 1.0000x reference)
#include <cuda_runtime.h>
#include <cuda_fp16.h>
#include <mma.h>
#include <cstddef>
#include <cstdint>

using namespace nvcuda;

// ---------------------------------------------------------------------------
// Static scratch (padded to NPAD rows so gemm loads/stores are branch-free)
// ---------------------------------------------------------------------------
#define NMAX 50000
#define NPAD 50176
#define CAP  192
#define CAP2 96

__device__ __half g_h1[(size_t)NPAD * 128];    // layer1 out, fp16
__device__ __half g_y16[(size_t)NPAD * 64];    // gemm message out y, fp16
__device__ float  g_r32[(size_t)NPAD * 64];    // gemm residual out r, fp32
__device__ __half g_h2[(size_t)NPAD * 64];     // h2 fp16
__device__ __half g_z16[(size_t)NPAD * 64];    // z fp16 (decoder input)
__device__ __half g_uv[(size_t)NPAD * 256];    // decoder [u128|v128] fp16

// split weights (hi rows [0,K), lo rows [K,2K)) + padded biases
__device__ __half g_ws2[256 * 128];
__device__ __half g_ws3[128 * 128];
__device__ __half g_wsd[128 * 256];
__device__ float  g_bias2[128];
__device__ float  g_bias3[128];
__device__ float  g_biasd[256];

// bucketed CSR (by dst, all edges) + obs-edge CSR (by src)
__device__ int  g_cursor[NMAX];
__device__ int2 g_csr[(size_t)NMAX * CAP];
__device__ int  g_cursor2[NMAX];
__device__ int2 g_csr2[(size_t)NMAX * CAP2];

// ---------------------------------------------------------------------------
// cp.async helpers
// ---------------------------------------------------------------------------
__device__ __forceinline__ void cp16(void* smem, const void* gptr) {
    unsigned int s = (unsigned int)__cvta_generic_to_shared(smem);
    asm volatile("cp.async.ca.shared.global [%0], [%1], 16;\n" :: "r"(s), "l"(gptr));
}
__device__ __forceinline__ void cp_commit() {
    asm volatile("cp.async.commit_group;\n");
}
template <int n>
__device__ __forceinline__ void cp_wait() {
    asm volatile("cp.async.wait_group %0;\n" :: "n"(n));
}

// ---------------------------------------------------------------------------
// Single prep kernel: all weight splits + all biases
// ---------------------------------------------------------------------------
__global__ void prep_all(const float* __restrict__ W2_rel, const float* __restrict__ W2_root,
                         const float* __restrict__ W3_rel, const float* __restrict__ W3_root,
                         const float* __restrict__ dW1,
                         const float* __restrict__ b2, const float* __restrict__ b3,
                         const float* __restrict__ db1,
                         __half* __restrict__ ws2, __half* __restrict__ ws3,
                         __half* __restrict__ wsd,
                         float* __restrict__ bias2, float* __restrict__ bias3,
                         float* __restrict__ biasd) {
    int i = blockIdx.x * blockDim.x + threadIdx.x;
    const int A = 128 * 128;
    const int B = 64 * 128;
    const int Cc = 64 * 256;
    if (i < A) {
        int k = i >> 7, j = i & 127;
        float v = (j < 64) ? W2_rel[k * 64 + j] : W2_root[k * 64 + (j - 64)];
        __half hi = __float2half_rn(v);
        ws2[(size_t)k * 128 + j] = hi;
        ws2[(size_t)(128 + k) * 128 + j] = __float2half_rn(v - __half2float(hi));
        return;
    }
    i -= A;
    if (i < B) {
        int k = i >> 7, j = i & 127;
        float v = (j < 64) ? W3_rel[k * 64 + j] : W3_root[k * 64 + (j - 64)];
        __half hi = __float2half_rn(v);
        ws3[(size_t)k * 128 + j] = hi;
        ws3[(size_t)(64 + k) * 128 + j] = __float2half_rn(v - __half2float(hi));
        return;
    }
    i -= B;
    if (i < Cc) {
        int k = i >> 8, j = i & 255;
        float v = dW1[k * 128 + (j & 127) + ((j >> 7) ? 64 * 128 : 0)];
        __half hi = __float2half_rn(v);
        wsd[(size_t)k * 256 + j] = hi;
        wsd[(size_t)(64 + k) * 256 + j] = __float2half_rn(v - __half2float(hi));
        return;
    }
    i -= Cc;
    if (i < 128) { bias2[i] = (i >= 64) ? b2[i - 64] : 0.f; return; }
    i -= 128;
    if (i < 128) { bias3[i] = (i >= 64) ? b3[i - 64] : 0.f; return; }
    i -= 128;
    if (i < 256) { biasd[i] = (i < 128) ? db1[i] : 0.f; return; }
}

// ---------------------------------------------------------------------------
// Merged CSR fill: dst-bucketed (all E edges) + src-bucketed obs edges
// ---------------------------------------------------------------------------
__global__ void fill_kernel(const int* __restrict__ src, const int* __restrict__ dst,
                            const float* __restrict__ ew,
                            int* __restrict__ cursor, int2* __restrict__ csr,
                            int* __restrict__ cursor2, int2* __restrict__ csr2,
                            int E, int OBS) {
    int e = blockIdx.x * blockDim.x + threadIdx.x;
    if (e >= E) return;
    int s = src[e];
    int d = dst[e];
    int p = atomicAdd(&cursor[d], 1);
    if (p < CAP) csr[(size_t)d * CAP + p] = make_int2(s, __float_as_int(ew[e]));
    if (e < OBS) {
        int q = atomicAdd(&cursor2[s], 1);
        if (q < CAP2) csr2[(size_t)s * CAP2 + q] = make_int2(d, e);
    }
}

// ---------------------------------------------------------------------------
// Fused layer-1: quad-gather + expand to fp16 (2 -> 128)
// ---------------------------------------------------------------------------
__global__ void layer1_fused(const int2* __restrict__ csr, const int* __restrict__ cnt,
                             const float* __restrict__ x,
                             const float* __restrict__ W1_rel,
                             const float* __restrict__ W1_root,
                             const float* __restrict__ b1,
                             __half* __restrict__ h1, int N) {
    int tid = blockIdx.x * blockDim.x + threadIdx.x;
    int n = tid >> 2;
    int l = tid & 3;
    if (n >= N) return;
    int deg = __ldg(cnt + n);
    const int2* bkt = csr + (size_t)n * CAP;
    float a0 = 0.f, a1 = 0.f;
    for (int i = l; i < deg; i += 4) {
        int2 p = __ldg(bkt + i);
        float w = __int_as_float(p.y);
        float2 xv = __ldg((const float2*)(x + 2 * (size_t)p.x));
        a0 += w * xv.x;
        a1 += w * xv.y;
    }
#pragma unroll
    for (int o = 1; o < 4; o <<= 1) {
        a0 += __shfl_xor_sync(0xFFFFFFFFu, a0, o);
        a1 += __shfl_xor_sync(0xFFFFFFFFu, a1, o);
    }
    float2 xv = __ldg((const float2*)(x + 2 * (size_t)n));
    __half* hp = h1 + (size_t)n * 128;
#pragma unroll 4
    for (int j = 0; j < 16; j++) {
        int f = l * 32 + 2 * j;
        float v0 = a0 * __ldg(W1_rel + f) + a1 * __ldg(W1_rel + 128 + f)
                 + xv.x * __ldg(W1_root + f) + xv.y * __ldg(W1_root + 128 + f) + __ldg(b1 + f);
        float v1 = a0 * __ldg(W1_rel + f + 1) + a1 * __ldg(W1_rel + 129 + f)
                 + xv.x * __ldg(W1_root + f + 1) + xv.y * __ldg(W1_root + 129 + f) + __ldg(b1 + f + 1);
        *(__half2*)(hp + f) = __halves2half2(
            __float2half_rn(fmaxf(v0, 0.f)), __float2half_rn(fmaxf(v1, 0.f)));
    }
}

// ---------------------------------------------------------------------------
// Pipelined wmma GEMM, split weights only.
//   C = H (fp16) @ (W_hi + W_lo) + bias.
//   M-tile 128, N-tile 128, K-tile 32 per step; one H tile feeds both W tiles.
// MODE 1: cols [0,64) -> fp16 Cy, cols [64,128) -> fp32 Cr.
// MODE 2: all OUT cols -> fp16 Cy (two-pass smem convert).
// ---------------------------------------------------------------------------
template <int K, int OUT, int MODE>
__global__ __launch_bounds__(256, 2) void gemm_pipe(const __half* __restrict__ Hs,
                                                    const __half* __restrict__ Ws,
                                                    const float* __restrict__ bias,
                                                    __half* __restrict__ Cy,
                                                    float* __restrict__ Cr) {
    constexpr int NKT = K / 32;        // steps
    constexpr int LDH = 40;            // 32 + 8 pad (halves)
    constexpr int LDW = 136;           // 128 + 8 pad
    constexpr int HBh = 128 * LDH;     // halves per H buffer
    constexpr int WBh = 32 * LDW;      // halves per W tile

    extern __shared__ char smem_raw[];
    __half* sh_h   = (__half*)smem_raw;                                  // [2][HBh]
    __half* sh_whi = (__half*)(smem_raw + 2 * HBh * 2);                  // [2][WBh]
    __half* sh_wlo = (__half*)(smem_raw + 2 * HBh * 2 + 2 * WBh * 2);    // [2][WBh]
    float*  sh_b   = (float*)(smem_raw + 2 * HBh * 2 + 4 * WBh * 2);     // 16*128
    float*  sh_c   = (float*)smem_raw;                                   // epilogue reuse

    int m0 = blockIdx.x * 128;
    int n0 = blockIdx.y * 128;
    int t = threadIdx.x;      // 256
    int warp = t >> 5;
    int wm = (warp & 3) * 32;        // 4 m-tiles of 32
    int wn = (warp >> 2) * 64;       // 2 n-tiles of 64

    // bias tile: 16 rows x 128 cols, all rows identical
    {
        int r = t >> 4, c8 = (t & 15) * 8;
        float4 b0 = *(const float4*)(bias + n0 + c8);
        float4 b1 = *(const float4*)(bias + n0 + c8 + 4);
        *(float4*)(sh_b + r * 128 + c8) = b0;
        *(float4*)(sh_b + r * 128 + c8 + 4) = b1;
    }

    auto load_step = [&](int kt, int buf) {
        int kc = kt * 32;
        __half* hb = sh_h + buf * HBh;
        __half* wh = sh_whi + buf * WBh;
        __half* wl = sh_wlo + buf * WBh;
#pragma unroll
        for (int i = 0; i < 2; i++) {
            int idx = t + i * 256;
            int row = idx >> 2, ch = idx & 3;
            cp16(hb + row * LDH + ch * 8, Hs + (size_t)(m0 + row) * K + kc + ch * 8);
        }
#pragma unroll
        for (int i = 0; i < 2; i++) {
            int idx = t + i * 256;
            int row = idx >> 4, ch = idx & 15;
            cp16(wh + row * LDW + ch * 8, Ws + (size_t)(kc + row) * OUT + n0 + ch * 8);
            cp16(wl + row * LDW + ch * 8, Ws + (size_t)(K + kc + row) * OUT + n0 + ch * 8);
        }
    };

    load_step(0, 0);
    cp_commit();

    __syncthreads();  // bias tile visible
    wmma::fragment<wmma::accumulator, 16, 16, 16, float> acc[2][4];
#pragma unroll
    for (int i = 0; i < 2; i++)
#pragma unroll
        for (int j = 0; j < 4; j++)
            wmma::load_matrix_sync(acc[i][j], sh_b + wn + j * 16, 128, wmma::mem_row_major);

    for (int step = 0; step < NKT; step++) {
        int cur = step & 1;
        if (step + 1 < NKT) load_step(step + 1, cur ^ 1);
        cp_commit();
        cp_wait<1>();
        __syncthreads();
        const __half* hb = sh_h + cur * HBh;
        const __half* wh = sh_whi + cur * WBh;
        const __half* wl = sh_wlo + cur * WBh;
#pragma unroll
        for (int kk = 0; kk < 32; kk += 16) {
            wmma::fragment<wmma::matrix_a, 16, 16, 16, __half, wmma::row_major> a0, a1;
            wmma::fragment<wmma::matrix_b, 16, 16, 16, __half, wmma::row_major> b[4];
            wmma::load_matrix_sync(a0, hb + (wm + 0) * LDH + kk, LDH);
            wmma::load_matrix_sync(a1, hb + (wm + 16) * LDH + kk, LDH);
#pragma unroll
            for (int j = 0; j < 4; j++)
                wmma::load_matrix_sync(b[j], wh + kk * LDW + wn + j * 16, LDW);
#pragma unroll
            for (int j = 0; j < 4; j++) {
                wmma::mma_sync(acc[0][j], a0, b[j], acc[0][j]);
                wmma::mma_sync(acc[1][j], a1, b[j], acc[1][j]);
            }
#pragma unroll
            for (int j = 0; j < 4; j++)
                wmma::load_matrix_sync(b[j], wl + kk * LDW + wn + j * 16, LDW);
#pragma unroll
            for (int j = 0; j < 4; j++) {
                wmma::mma_sync(acc[0][j], a0, b[j], acc[0][j]);
                wmma::mma_sync(acc[1][j], a1, b[j], acc[1][j]);
            }
        }
        __syncthreads();
    }

    if constexpr (MODE == 1) {
        if (wn == 0) {
#pragma unroll
            for (int i = 0; i < 2; i++)
#pragma unroll
                for (int j = 0; j < 4; j++)
                    wmma::store_matrix_sync(sh_c + (size_t)(wm + i * 16) * 64 + j * 16,
                                            acc[i][j], 64, wmma::mem_row_major);
        } else {
#pragma unroll
            for (int i = 0; i < 2; i++)
#pragma unroll
                for (int j = 0; j < 4; j++)
                    wmma::store_matrix_sync(Cr + (size_t)(m0 + wm + i * 16) * 64 + j * 16,
                                            acc[i][j], 64, wmma::mem_row_major);
        }
        __syncthreads();
        for (int idx = t; idx < 128 * 32; idx += 256) {
            int row = idx >> 5, cp = (idx & 31) * 2;
            float2 v = *(const float2*)(sh_c + (size_t)row * 64 + cp);
            *(__half2*)(Cy + (size_t)(m0 + row) * 64 + cp) =
                __halves2half2(__float2half_rn(v.x), __float2half_rn(v.y));
        }
    } else {
#pragma unroll
        for (int g = 0; g < 2; g++) {
            if ((warp >> 2) == g) {
#pragma unroll
                for (int i = 0; i < 2; i++)
#pragma unroll
                    for (int j = 0; j < 4; j++)
                        wmma::store_matrix_sync(sh_c + (size_t)(wm + i * 16) * 64 + j * 16,
                                                acc[i][j], 64, wmma::mem_row_major);
            }
            __syncthreads();
            for (int idx = t; idx < 128 * 64; idx += 256) {
                int row = idx >> 6, col = idx & 63;
                Cy[(size_t)(m0 + row) * OUT + n0 + g * 64 + col] = __float2half_rn(sh_c[idx]);
            }
            __syncthreads();
        }
    }
}

// ---------------------------------------------------------------------------
// Fused gather + residual + act. y16 fp16 [NPAD x 64]; r32 fp32 [NPAD x 64].
// 8 lanes/node, lane owns 8 feats. Optional fp32 out (z) / fp16 out.
// ---------------------------------------------------------------------------
__global__ void gather64(const int2* __restrict__ csr, const int* __restrict__ cnt,
                         const __half* __restrict__ y16, const float* __restrict__ r32,
                         float* __restrict__ out32, __half* __restrict__ out16,
                         int N, int do_relu) {
    int node = blockIdx.x * 32 + (threadIdx.x >> 3);
    int c = threadIdx.x & 7;
    if (node >= N) return;
    int deg = __ldg(cnt + node);
    const int2* bkt = csr + (size_t)node * CAP;
    float4 a0 = make_float4(0, 0, 0, 0);
    float4 a1 = make_float4(0, 0, 0, 0);

    auto accum = [&](int2 p) {
        float w = __int_as_float(p.y);
        uint4 hv = __ldg((const uint4*)(y16 + (size_t)p.x * 64) + c);
        float2 f0 = __half22float2(*(const half2*)&hv.x);
        float2 f1 = __half22float2(*(const half2*)&hv.y);
        float2 f2 = __half22float2(*(const half2*)&hv.z);
        float2 f3 = __half22float2(*(const half2*)&hv.w);
        a0.x += w * f0.x; a0.y += w * f0.y; a0.z += w * f1.x; a0.w += w * f1.y;
        a1.x += w * f2.x; a1.y += w * f2.y; a1.z += w * f3.x; a1.w += w * f3.y;
    };

    int i = 0;
    for (; i + 2 <= deg; i += 2) {
        int2 p0 = __ldg(bkt + i);
        int2 p1 = __ldg(bkt + i + 1);
        accum(p0);
        accum(p1);
    }
    if (i < deg) accum(__ldg(bkt + i));

    const float4* rp = (const float4*)(r32 + (size_t)node * 64);
    float4 rv0 = __ldg(rp + 2 * c);
    float4 rv1 = __ldg(rp + 2 * c + 1);
    a0.x += rv0.x; a0.y += rv0.y; a0.z += rv0.z; a0.w += rv0.w;
    a1.x += rv1.x; a1.y += rv1.y; a1.z += rv1.z; a1.w += rv1.w;
    if (do_relu) {
        a0.x = fmaxf(a0.x, 0.f); a0.y = fmaxf(a0.y, 0.f);
        a0.z = fmaxf(a0.z, 0.f); a0.w = fmaxf(a0.w, 0.f);
        a1.x = fmaxf(a1.x, 0.f); a1.y = fmaxf(a1.y, 0.f);
        a1.z = fmaxf(a1.z, 0.f); a1.w = fmaxf(a1.w, 0.f);
    }
    if (out32) {
        float4* op = (float4*)(out32 + (size_t)node * 64);
        op[2 * c] = a0;
        op[2 * c + 1] = a1;
    }
    if (out16) {
        __half* sp = out16 + (size_t)node * 64;
        int f = 8 * c;
        *(__half2*)(sp + f + 0) = __halves2half2(__float2half_rn(a0.x), __float2half_rn(a0.y));
        *(__half2*)(sp + f + 2) = __halves2half2(__float2half_rn(a0.z), __float2half_rn(a0.w));
        *(__half2*)(sp + f + 4) = __halves2half2(__float2half_rn(a1.x), __float2half_rn(a1.y));
        *(__half2*)(sp + f + 6) = __halves2half2(__float2half_rn(a1.z), __float2half_rn(a1.w));
    }
}

// ---------------------------------------------------------------------------
// Grouped decoder: obs edges bucketed by source node. 16 lanes per src node;
// u[s] and dec_W2 loaded ONCE into registers, then loop edges reading v[d].
// pred[e] = relu(u[s]+v[d]) . dec_W2 + dec_b2 ; duplicated at e+OBS.
// ---------------------------------------------------------------------------
__global__ void decode_grouped(const int2* __restrict__ csr2, const int* __restrict__ cnt2,
                               const __half* __restrict__ uv,
                               const float* __restrict__ W2, const float* __restrict__ b2,
                               float* __restrict__ pred, int N, int OBS) {
    int node = blockIdx.x * 16 + (threadIdx.x >> 4);
    int c = threadIdx.x & 15;
    if (node >= N) return;
    int deg = __ldg(cnt2 + node);
    if (deg == 0) return;

    uint4 ub = __ldg((const uint4*)(uv + (size_t)node * 256) + c);
    float4 w0 = __ldg((const float4*)W2 + 2 * c);
    float4 w1 = __ldg((const float4*)W2 + 2 * c + 1);
    float bias = __ldg(b2);
    float2 fu0 = __half22float2(*(const half2*)&ub.x);
    float2 fu1 = __half22float2(*(const half2*)&ub.y);
    float2 fu2 = __half22float2(*(const half2*)&ub.z);
    float2 fu3 = __half22float2(*(const half2*)&ub.w);

    const int2* bkt = csr2 + (size_t)node * CAP2;

    auto edge_dot = [&](uint4 vb) -> float {
        float2 fv0 = __half22float2(*(const half2*)&vb.x);
        float2 fv1 = __half22float2(*(const half2*)&vb.y);
        float2 fv2 = __half22float2(*(const half2*)&vb.z);
        float2 fv3 = __half22float2(*(const half2*)&vb.w);
        return fmaxf(fu0.x + fv0.x, 0.f) * w0.x + fmaxf(fu0.y + fv0.y, 0.f) * w0.y
             + fmaxf(fu1.x + fv1.x, 0.f) * w0.z + fmaxf(fu1.y + fv1.y, 0.f) * w0.w
             + fmaxf(fu2.x + fv2.x, 0.f) * w1.x + fmaxf(fu2.y + fv2.y, 0.f) * w1.y
             + fmaxf(fu3.x + fv3.x, 0.f) * w1.z + fmaxf(fu3.y + fv3.y, 0.f) * w1.w;
    };

    int i = 0;
    for (; i + 2 <= deg; i += 2) {
        int2 p0 = __ldg(bkt + i);
        int2 p1 = __ldg(bkt + i + 1);
        uint4 v0 = __ldg((const uint4*)(uv + (size_t)p0.x * 256 + 128) + c);
        uint4 v1 = __ldg((const uint4*)(uv + (size_t)p1.x * 256 + 128) + c);
        float acc0 = edge_dot(v0);
        float acc1 = edge_dot(v1);
#pragma unroll
        for (int o = 8; o > 0; o >>= 1) {
            acc0 += __shfl_xor_sync(0xFFFFFFFFu, acc0, o);
            acc1 += __shfl_xor_sync(0xFFFFFFFFu, acc1, o);
        }
        if (c == 0) {
            float q0 = acc0 + bias, q1 = acc1 + bias;
            pred[p0.y] = q0;
            pred[p0.y + OBS] = q0;
            pred[p1.y] = q1;
            pred[p1.y + OBS] = q1;
        }
    }
    if (i < deg) {
        int2 p0 = __ldg(bkt + i);
        uint4 v0 = __ldg((const uint4*)(uv + (size_t)p0.x * 256 + 128) + c);
        float acc0 = edge_dot(v0);
#pragma unroll
        for (int o = 8; o > 0; o >>= 1)
            acc0 += __shfl_xor_sync(0xFFFFFFFFu, acc0, o);
        if (c == 0) {
            float q0 = acc0 + bias;
            pred[p0.y] = q0;
            pred[p0.y + OBS] = q0;
        }
    }
}

// ---------------------------------------------------------------------------
// Launch
// ---------------------------------------------------------------------------
extern "C" void kernel_launch(void* const* d_in, const int* in_sizes, int n_in,
                              void* d_out, int out_size) {
    const float* x       = (const float*)d_in[0];
    const int*   ei      = (const int*)d_in[1];
    const float* ew      = (const float*)d_in[2];
    const float* W1_rel  = (const float*)d_in[4];
    const float* b1      = (const float*)d_in[5];
    const float* W1_root = (const float*)d_in[6];
    const float* W2_rel  = (const float*)d_in[7];
    const float* b2      = (const float*)d_in[8];
    const float* W2_root = (const float*)d_in[9];
    const float* W3_rel  = (const float*)d_in[10];
    const float* b3      = (const float*)d_in[11];
    const float* W3_root = (const float*)d_in[12];
    const float* dW1     = (const float*)d_in[13];
    const float* db1     = (const float*)d_in[14];
    const float* dW2     = (const float*)d_in[15];
    const float* db2     = (const float*)d_in[16];

    int N   = in_sizes[0] / 2;
    int E   = in_sizes[2];
    int OBS = E / 2;

    const int* src = ei;
    const int* dst = ei + E;

    float* out = (float*)d_out;
    float* z   = out + 2 * (size_t)OBS;

    float *r32, *bias2, *bias3, *biasd;
    __half *h1, *y16, *h2, *z16, *uv, *ws2, *ws3, *wsd;
    int *cursor, *cursor2;
    int2 *csr, *csr2;
    cudaGetSymbolAddress((void**)&h1,      g_h1);
    cudaGetSymbolAddress((void**)&y16,     g_y16);
    cudaGetSymbolAddress((void**)&r32,     g_r32);
    cudaGetSymbolAddress((void**)&h2,      g_h2);
    cudaGetSymbolAddress((void**)&z16,     g_z16);
    cudaGetSymbolAddress((void**)&uv,      g_uv);
    cudaGetSymbolAddress((void**)&ws2,     g_ws2);
    cudaGetSymbolAddress((void**)&ws3,     g_ws3);
    cudaGetSymbolAddress((void**)&wsd,     g_wsd);
    cudaGetSymbolAddress((void**)&bias2,   g_bias2);
    cudaGetSymbolAddress((void**)&bias3,   g_bias3);
    cudaGetSymbolAddress((void**)&biasd,   g_biasd);
    cudaGetSymbolAddress((void**)&cursor,  g_cursor);
    cudaGetSymbolAddress((void**)&cursor2, g_cursor2);
    cudaGetSymbolAddress((void**)&csr,     g_csr);
    cudaGetSymbolAddress((void**)&csr2,    g_csr2);

    // dyn smem: 2 H bufs + 2x2 W bufs + bias tile
    const int SMEM = 2 * (128 * 40) * 2 + 4 * (32 * 136) * 2 + 16 * 128 * 4;  // 63488
    cudaFuncSetAttribute(gemm_pipe<128, 128, 1>,
                         cudaFuncAttributeMaxDynamicSharedMemorySize, SMEM);
    cudaFuncSetAttribute(gemm_pipe<64, 128, 1>,
                         cudaFuncAttributeMaxDynamicSharedMemorySize, SMEM);
    cudaFuncSetAttribute(gemm_pipe<64, 256, 2>,
                         cudaFuncAttributeMaxDynamicSharedMemorySize, SMEM);

    const int TB = 256;
    int eb = (E + TB - 1) / TB;
    int mb128 = (N + 127) / 128;

    // ---- prep (1 launch) ----
    {
        int total = 128 * 128 + 64 * 128 + 64 * 256 + 128 + 128 + 256;
        prep_all<<<(total + TB - 1) / TB, TB>>>(W2_rel, W2_root, W3_rel, W3_root, dW1,
                                                b2, b3, db1, ws2, ws3, wsd,
                                                bias2, bias3, biasd);
    }

    // ---- Bucketed CSRs (dst-keyed full graph + src-keyed obs edges) ----
    cudaMemsetAsync(cursor, 0, (size_t)N * sizeof(int));
    cudaMemsetAsync(cursor2, 0, (size_t)N * sizeof(int));
    fill_kernel<<<eb, TB>>>(src, dst, ew, cursor, csr, cursor2, csr2, E, OBS);

    // ---- Layer 1 fused ----
    layer1_fused<<<(N * 4 + TB - 1) / TB, TB>>>(csr, cursor, x, W1_rel, W1_root, b1, h1, N);

    // ---- Layer 2: gemm (y fp16 | r fp32) + fused gather ----
    gemm_pipe<128, 128, 1><<<dim3(mb128, 1), 256, SMEM>>>(h1, ws2, bias2, y16, r32);
    gather64<<<(N + 31) / 32, TB>>>(csr, cursor, y16, r32, nullptr, h2, N, 1);

    // ---- Layer 3 ----
    gemm_pipe<64, 128, 1><<<dim3(mb128, 1), 256, SMEM>>>(h2, ws3, bias3, y16, r32);
    gather64<<<(N + 31) / 32, TB>>>(csr, cursor, y16, r32, z, z16, N, 0);

    // ---- Decoder: gemm -> grouped edge decode ----
    gemm_pipe<64, 256, 2><<<dim3(mb128, 2), 256, SMEM>>>(z16, wsd, biasd, uv, nullptr);
    decode_grouped<<<(N + 15) / 16, TB>>>(csr2, cursor2, uv, dW2, db2, out, N, OBS);
}

// round 11
// speedup vs baseline: 1.0318x; 1.0318x over previous
#include <cuda_runtime.h>
#include <cuda_fp16.h>
#include <mma.h>
#include <cstddef>
#include <cstdint>

using namespace nvcuda;

// ---------------------------------------------------------------------------
// Static scratch (padded to NPAD rows so gemm loads/stores are branch-free)
// ---------------------------------------------------------------------------
#define NMAX 50000
#define NPAD 50176
#define CAP  192

__device__ __half g_h1[(size_t)NPAD * 128];    // layer1 out, fp16
__device__ __half g_y16[(size_t)NPAD * 64];    // gemm message out y, fp16
__device__ float  g_r32[(size_t)NPAD * 64];    // gemm residual out r, fp32
__device__ __half g_h2[(size_t)NPAD * 64];     // h2 fp16
__device__ __half g_z16[(size_t)NPAD * 64];    // z fp16 (decoder input)
__device__ __half g_uv[(size_t)NPAD * 256];    // decoder [u128|v128] fp16

// split weights (hi rows [0,K), lo rows [K,2K)) + padded biases
__device__ __half g_ws2[256 * 128];
__device__ __half g_ws3[128 * 128];
__device__ __half g_wsd[128 * 256];
__device__ float  g_bias2[128];
__device__ float  g_bias3[128];
__device__ float  g_biasd[256];

// bucketed CSR (by dst, all edges)
__device__ int  g_cursor[NMAX];
__device__ int2 g_csr[(size_t)NMAX * CAP];

// ---------------------------------------------------------------------------
// cp.async helpers
// ---------------------------------------------------------------------------
__device__ __forceinline__ void cp16(void* smem, const void* gptr) {
    unsigned int s = (unsigned int)__cvta_generic_to_shared(smem);
    asm volatile("cp.async.ca.shared.global [%0], [%1], 16;\n" :: "r"(s), "l"(gptr));
}
__device__ __forceinline__ void cp_commit() {
    asm volatile("cp.async.commit_group;\n");
}
template <int n>
__device__ __forceinline__ void cp_wait() {
    asm volatile("cp.async.wait_group %0;\n" :: "n"(n));
}

// ---------------------------------------------------------------------------
// Single prep kernel: zero CSR cursors + all weight splits + all biases
// ---------------------------------------------------------------------------
__global__ void prep_all(const float* __restrict__ W2_rel, const float* __restrict__ W2_root,
                         const float* __restrict__ W3_rel, const float* __restrict__ W3_root,
                         const float* __restrict__ dW1,
                         const float* __restrict__ b2, const float* __restrict__ b3,
                         const float* __restrict__ db1,
                         __half* __restrict__ ws2, __half* __restrict__ ws3,
                         __half* __restrict__ wsd,
                         float* __restrict__ bias2, float* __restrict__ bias3,
                         float* __restrict__ biasd,
                         int* __restrict__ cursor, int N) {
    int i = blockIdx.x * blockDim.x + threadIdx.x;
    if (i < N) cursor[i] = 0;   // fold the memset in
    const int A = 128 * 128;
    const int B = 64 * 128;
    const int Cc = 64 * 256;
    if (i < A) {
        int k = i >> 7, j = i & 127;
        float v = (j < 64) ? W2_rel[k * 64 + j] : W2_root[k * 64 + (j - 64)];
        __half hi = __float2half_rn(v);
        ws2[(size_t)k * 128 + j] = hi;
        ws2[(size_t)(128 + k) * 128 + j] = __float2half_rn(v - __half2float(hi));
        return;
    }
    i -= A;
    if (i < B) {
        int k = i >> 7, j = i & 127;
        float v = (j < 64) ? W3_rel[k * 64 + j] : W3_root[k * 64 + (j - 64)];
        __half hi = __float2half_rn(v);
        ws3[(size_t)k * 128 + j] = hi;
        ws3[(size_t)(64 + k) * 128 + j] = __float2half_rn(v - __half2float(hi));
        return;
    }
    i -= B;
    if (i < Cc) {
        int k = i >> 8, j = i & 255;
        float v = dW1[k * 128 + (j & 127) + ((j >> 7) ? 64 * 128 : 0)];
        __half hi = __float2half_rn(v);
        wsd[(size_t)k * 256 + j] = hi;
        wsd[(size_t)(64 + k) * 256 + j] = __float2half_rn(v - __half2float(hi));
        return;
    }
    i -= Cc;
    if (i < 128) { bias2[i] = (i >= 64) ? b2[i - 64] : 0.f; return; }
    i -= 128;
    if (i < 128) { bias3[i] = (i >= 64) ? b3[i - 64] : 0.f; return; }
    i -= 128;
    if (i < 256) { biasd[i] = (i < 128) ? db1[i] : 0.f; return; }
}

// ---------------------------------------------------------------------------
// Bucketed CSR fill
// ---------------------------------------------------------------------------
__global__ void fill_kernel(const int* __restrict__ src, const int* __restrict__ dst,
                            const float* __restrict__ ew, int* __restrict__ cursor,
                            int2* __restrict__ csr, int E) {
    int e = blockIdx.x * blockDim.x + threadIdx.x;
    if (e >= E) return;
    int d = dst[e];
    int p = atomicAdd(&cursor[d], 1);
    if (p < CAP) csr[(size_t)d * CAP + p] = make_int2(src[e], __float_as_int(ew[e]));
}

// ---------------------------------------------------------------------------
// Fused layer-1: quad-gather + expand to fp16 (2 -> 128)
// ---------------------------------------------------------------------------
__global__ void layer1_fused(const int2* __restrict__ csr, const int* __restrict__ cnt,
                             const float* __restrict__ x,
                             const float* __restrict__ W1_rel,
                             const float* __restrict__ W1_root,
                             const float* __restrict__ b1,
                             __half* __restrict__ h1, int N) {
    int tid = blockIdx.x * blockDim.x + threadIdx.x;
    int n = tid >> 2;
    int l = tid & 3;
    if (n >= N) return;
    int deg = __ldg(cnt + n);
    const int2* bkt = csr + (size_t)n * CAP;
    float a0 = 0.f, a1 = 0.f;
    for (int i = l; i < deg; i += 4) {
        int2 p = __ldg(bkt + i);
        float w = __int_as_float(p.y);
        float2 xv = __ldg((const float2*)(x + 2 * (size_t)p.x));
        a0 += w * xv.x;
        a1 += w * xv.y;
    }
#pragma unroll
    for (int o = 1; o < 4; o <<= 1) {
        a0 += __shfl_xor_sync(0xFFFFFFFFu, a0, o);
        a1 += __shfl_xor_sync(0xFFFFFFFFu, a1, o);
    }
    float2 xv = __ldg((const float2*)(x + 2 * (size_t)n));
    __half* hp = h1 + (size_t)n * 128;
#pragma unroll 4
    for (int j = 0; j < 16; j++) {
        int f = l * 32 + 2 * j;
        float v0 = a0 * __ldg(W1_rel + f) + a1 * __ldg(W1_rel + 128 + f)
                 + xv.x * __ldg(W1_root + f) + xv.y * __ldg(W1_root + 128 + f) + __ldg(b1 + f);
        float v1 = a0 * __ldg(W1_rel + f + 1) + a1 * __ldg(W1_rel + 129 + f)
                 + xv.x * __ldg(W1_root + f + 1) + xv.y * __ldg(W1_root + 129 + f) + __ldg(b1 + f + 1);
        *(__half2*)(hp + f) = __halves2half2(
            __float2half_rn(fmaxf(v0, 0.f)), __float2half_rn(fmaxf(v1, 0.f)));
    }
}

// ---------------------------------------------------------------------------
// Pipelined wmma GEMM, split weights only.
//   C = H (fp16) @ (W_hi + W_lo) + bias.
//   M-tile 128, N-tile 128, K-tile 32 per step; one H tile feeds both W tiles.
// MODE 1: cols [0,64) -> fp16 Cy, cols [64,128) -> fp32 Cr.
// MODE 2: all OUT cols -> fp16 Cy (two-pass smem convert).
// ---------------------------------------------------------------------------
template <int K, int OUT, int MODE>
__global__ __launch_bounds__(256, 2) void gemm_pipe(const __half* __restrict__ Hs,
                                                    const __half* __restrict__ Ws,
                                                    const float* __restrict__ bias,
                                                    __half* __restrict__ Cy,
                                                    float* __restrict__ Cr) {
    constexpr int NKT = K / 32;        // steps
    constexpr int LDH = 40;            // 32 + 8 pad (halves)
    constexpr int LDW = 136;           // 128 + 8 pad
    constexpr int HBh = 128 * LDH;     // halves per H buffer
    constexpr int WBh = 32 * LDW;      // halves per W tile

    extern __shared__ char smem_raw[];
    __half* sh_h   = (__half*)smem_raw;                                  // [2][HBh]
    __half* sh_whi = (__half*)(smem_raw + 2 * HBh * 2);                  // [2][WBh]
    __half* sh_wlo = (__half*)(smem_raw + 2 * HBh * 2 + 2 * WBh * 2);    // [2][WBh]
    float*  sh_b   = (float*)(smem_raw + 2 * HBh * 2 + 4 * WBh * 2);     // 16*128
    float*  sh_c   = (float*)smem_raw;                                   // epilogue reuse

    int m0 = blockIdx.x * 128;
    int n0 = blockIdx.y * 128;
    int t = threadIdx.x;      // 256
    int warp = t >> 5;
    int wm = (warp & 3) * 32;        // 4 m-tiles of 32
    int wn = (warp >> 2) * 64;       // 2 n-tiles of 64

    // bias tile: 16 rows x 128 cols, all rows identical
    {
        int r = t >> 4, c8 = (t & 15) * 8;
        float4 b0 = *(const float4*)(bias + n0 + c8);
        float4 b1 = *(const float4*)(bias + n0 + c8 + 4);
        *(float4*)(sh_b + r * 128 + c8) = b0;
        *(float4*)(sh_b + r * 128 + c8 + 4) = b1;
    }

    auto load_step = [&](int kt, int buf) {
        int kc = kt * 32;
        __half* hb = sh_h + buf * HBh;
        __half* wh = sh_whi + buf * WBh;
        __half* wl = sh_wlo + buf * WBh;
#pragma unroll
        for (int i = 0; i < 2; i++) {
            int idx = t + i * 256;
            int row = idx >> 2, ch = idx & 3;
            cp16(hb + row * LDH + ch * 8, Hs + (size_t)(m0 + row) * K + kc + ch * 8);
        }
#pragma unroll
        for (int i = 0; i < 2; i++) {
            int idx = t + i * 256;
            int row = idx >> 4, ch = idx & 15;
            cp16(wh + row * LDW + ch * 8, Ws + (size_t)(kc + row) * OUT + n0 + ch * 8);
            cp16(wl + row * LDW + ch * 8, Ws + (size_t)(K + kc + row) * OUT + n0 + ch * 8);
        }
    };

    load_step(0, 0);
    cp_commit();

    __syncthreads();  // bias tile visible
    wmma::fragment<wmma::accumulator, 16, 16, 16, float> acc[2][4];
#pragma unroll
    for (int i = 0; i < 2; i++)
#pragma unroll
        for (int j = 0; j < 4; j++)
            wmma::load_matrix_sync(acc[i][j], sh_b + wn + j * 16, 128, wmma::mem_row_major);

    for (int step = 0; step < NKT; step++) {
        int cur = step & 1;
        if (step + 1 < NKT) load_step(step + 1, cur ^ 1);
        cp_commit();
        cp_wait<1>();
        __syncthreads();
        const __half* hb = sh_h + cur * HBh;
        const __half* wh = sh_whi + cur * WBh;
        const __half* wl = sh_wlo + cur * WBh;
#pragma unroll
        for (int kk = 0; kk < 32; kk += 16) {
            wmma::fragment<wmma::matrix_a, 16, 16, 16, __half, wmma::row_major> a0, a1;
            wmma::fragment<wmma::matrix_b, 16, 16, 16, __half, wmma::row_major> b[4];
            wmma::load_matrix_sync(a0, hb + (wm + 0) * LDH + kk, LDH);
            wmma::load_matrix_sync(a1, hb + (wm + 16) * LDH + kk, LDH);
#pragma unroll
            for (int j = 0; j < 4; j++)
                wmma::load_matrix_sync(b[j], wh + kk * LDW + wn + j * 16, LDW);
#pragma unroll
            for (int j = 0; j < 4; j++) {
                wmma::mma_sync(acc[0][j], a0, b[j], acc[0][j]);
                wmma::mma_sync(acc[1][j], a1, b[j], acc[1][j]);
            }
#pragma unroll
            for (int j = 0; j < 4; j++)
                wmma::load_matrix_sync(b[j], wl + kk * LDW + wn + j * 16, LDW);
#pragma unroll
            for (int j = 0; j < 4; j++) {
                wmma::mma_sync(acc[0][j], a0, b[j], acc[0][j]);
                wmma::mma_sync(acc[1][j], a1, b[j], acc[1][j]);
            }
        }
        __syncthreads();
    }

    if constexpr (MODE == 1) {
        if (wn == 0) {
#pragma unroll
            for (int i = 0; i < 2; i++)
#pragma unroll
                for (int j = 0; j < 4; j++)
                    wmma::store_matrix_sync(sh_c + (size_t)(wm + i * 16) * 64 + j * 16,
                                            acc[i][j], 64, wmma::mem_row_major);
        } else {
#pragma unroll
            for (int i = 0; i < 2; i++)
#pragma unroll
                for (int j = 0; j < 4; j++)
                    wmma::store_matrix_sync(Cr + (size_t)(m0 + wm + i * 16) * 64 + j * 16,
                                            acc[i][j], 64, wmma::mem_row_major);
        }
        __syncthreads();
        for (int idx = t; idx < 128 * 32; idx += 256) {
            int row = idx >> 5, cp = (idx & 31) * 2;
            float2 v = *(const float2*)(sh_c + (size_t)row * 64 + cp);
            *(__half2*)(Cy + (size_t)(m0 + row) * 64 + cp) =
                __halves2half2(__float2half_rn(v.x), __float2half_rn(v.y));
        }
    } else {
#pragma unroll
        for (int g = 0; g < 2; g++) {
            if ((warp >> 2) == g) {
#pragma unroll
                for (int i = 0; i < 2; i++)
#pragma unroll
                    for (int j = 0; j < 4; j++)
                        wmma::store_matrix_sync(sh_c + (size_t)(wm + i * 16) * 64 + j * 16,
                                                acc[i][j], 64, wmma::mem_row_major);
            }
            __syncthreads();
            for (int idx = t; idx < 128 * 64; idx += 256) {
                int row = idx >> 6, col = idx & 63;
                Cy[(size_t)(m0 + row) * OUT + n0 + g * 64 + col] = __float2half_rn(sh_c[idx]);
            }
            __syncthreads();
        }
    }
}

// ---------------------------------------------------------------------------
// Fused gather + residual + act. y16 fp16 [NPAD x 64]; r32 fp32 [NPAD x 64].
// 8 lanes/node, lane owns 8 feats. Optional fp32 out (z) / fp16 out.
// ---------------------------------------------------------------------------
__global__ void gather64(const int2* __restrict__ csr, const int* __restrict__ cnt,
                         const __half* __restrict__ y16, const float* __restrict__ r32,
                         float* __restrict__ out32, __half* __restrict__ out16,
                         int N, int do_relu) {
    int node = blockIdx.x * 32 + (threadIdx.x >> 3);
    int c = threadIdx.x & 7;
    if (node >= N) return;
    int deg = __ldg(cnt + node);
    const int2* bkt = csr + (size_t)node * CAP;
    float4 a0 = make_float4(0, 0, 0, 0);
    float4 a1 = make_float4(0, 0, 0, 0);

    auto accum = [&](int2 p) {
        float w = __int_as_float(p.y);
        uint4 hv = __ldg((const uint4*)(y16 + (size_t)p.x * 64) + c);
        float2 f0 = __half22float2(*(const half2*)&hv.x);
        float2 f1 = __half22float2(*(const half2*)&hv.y);
        float2 f2 = __half22float2(*(const half2*)&hv.z);
        float2 f3 = __half22float2(*(const half2*)&hv.w);
        a0.x += w * f0.x; a0.y += w * f0.y; a0.z += w * f1.x; a0.w += w * f1.y;
        a1.x += w * f2.x; a1.y += w * f2.y; a1.z += w * f3.x; a1.w += w * f3.y;
    };

    int i = 0;
    for (; i + 2 <= deg; i += 2) {
        int2 p0 = __ldg(bkt + i);
        int2 p1 = __ldg(bkt + i + 1);
        accum(p0);
        accum(p1);
    }
    if (i < deg) accum(__ldg(bkt + i));

    const float4* rp = (const float4*)(r32 + (size_t)node * 64);
    float4 rv0 = __ldg(rp + 2 * c);
    float4 rv1 = __ldg(rp + 2 * c + 1);
    a0.x += rv0.x; a0.y += rv0.y; a0.z += rv0.z; a0.w += rv0.w;
    a1.x += rv1.x; a1.y += rv1.y; a1.z += rv1.z; a1.w += rv1.w;
    if (do_relu) {
        a0.x = fmaxf(a0.x, 0.f); a0.y = fmaxf(a0.y, 0.f);
        a0.z = fmaxf(a0.z, 0.f); a0.w = fmaxf(a0.w, 0.f);
        a1.x = fmaxf(a1.x, 0.f); a1.y = fmaxf(a1.y, 0.f);
        a1.z = fmaxf(a1.z, 0.f); a1.w = fmaxf(a1.w, 0.f);
    }
    if (out32) {
        float4* op = (float4*)(out32 + (size_t)node * 64);
        op[2 * c] = a0;
        op[2 * c + 1] = a1;
    }
    if (out16) {
        __half* sp = out16 + (size_t)node * 64;
        int f = 8 * c;
        *(__half2*)(sp + f + 0) = __halves2half2(__float2half_rn(a0.x), __float2half_rn(a0.y));
        *(__half2*)(sp + f + 2) = __halves2half2(__float2half_rn(a0.z), __float2half_rn(a0.w));
        *(__half2*)(sp + f + 4) = __halves2half2(__float2half_rn(a1.x), __float2half_rn(a1.y));
        *(__half2*)(sp + f + 6) = __halves2half2(__float2half_rn(a1.z), __float2half_rn(a1.w));
    }
}

// ---------------------------------------------------------------------------
// Decoder: pred[e] = relu(u[s]+v[d]) . dec_W2 + dec_b2 ; duplicated.
// Flat per-edge: 16 threads/edge (u table is L2-resident; re-reads are cheap).
// ---------------------------------------------------------------------------
__global__ void decode_edges_h(const int* __restrict__ src, const int* __restrict__ dst,
                               const __half* __restrict__ uv,
                               const float* __restrict__ W2, const float* __restrict__ b2,
                               float* __restrict__ pred, int OBS) {
    int gt = blockIdx.x * blockDim.x + threadIdx.x;
    int e = gt >> 4;
    int c = gt & 15;
    if (e >= OBS) return;
    int s = src[e];
    int d = dst[e];
    uint4 ub = __ldg((const uint4*)(uv + (size_t)s * 256) + c);
    uint4 vb = __ldg((const uint4*)(uv + (size_t)d * 256 + 128) + c);
    float4 w0 = __ldg((const float4*)W2 + 2 * c);
    float4 w1 = __ldg((const float4*)W2 + 2 * c + 1);

    float2 fu0 = __half22float2(*(const half2*)&ub.x);
    float2 fu1 = __half22float2(*(const half2*)&ub.y);
    float2 fu2 = __half22float2(*(const half2*)&ub.z);
    float2 fu3 = __half22float2(*(const half2*)&ub.w);
    float2 fv0 = __half22float2(*(const half2*)&vb.x);
    float2 fv1 = __half22float2(*(const half2*)&vb.y);
    float2 fv2 = __half22float2(*(const half2*)&vb.z);
    float2 fv3 = __half22float2(*(const half2*)&vb.w);

    float acc = fmaxf(fu0.x + fv0.x, 0.f) * w0.x + fmaxf(fu0.y + fv0.y, 0.f) * w0.y
              + fmaxf(fu1.x + fv1.x, 0.f) * w0.z + fmaxf(fu1.y + fv1.y, 0.f) * w0.w
              + fmaxf(fu2.x + fv2.x, 0.f) * w1.x + fmaxf(fu2.y + fv2.y, 0.f) * w1.y
              + fmaxf(fu3.x + fv3.x, 0.f) * w1.z + fmaxf(fu3.y + fv3.y, 0.f) * w1.w;
#pragma unroll
    for (int o = 8; o > 0; o >>= 1) acc += __shfl_xor_sync(0xFFFFFFFFu, acc, o);
    if (c == 0) {
        float p = acc + __ldg(b2);
        pred[e] = p;
        pred[e + OBS] = p;
    }
}

// ---------------------------------------------------------------------------
// Launch
// ---------------------------------------------------------------------------
extern "C" void kernel_launch(void* const* d_in, const int* in_sizes, int n_in,
                              void* d_out, int out_size) {
    const float* x       = (const float*)d_in[0];
    const int*   ei      = (const int*)d_in[1];
    const float* ew      = (const float*)d_in[2];
    const float* W1_rel  = (const float*)d_in[4];
    const float* b1      = (const float*)d_in[5];
    const float* W1_root = (const float*)d_in[6];
    const float* W2_rel  = (const float*)d_in[7];
    const float* b2      = (const float*)d_in[8];
    const float* W2_root = (const float*)d_in[9];
    const float* W3_rel  = (const float*)d_in[10];
    const float* b3      = (const float*)d_in[11];
    const float* W3_root = (const float*)d_in[12];
    const float* dW1     = (const float*)d_in[13];
    const float* db1     = (const float*)d_in[14];
    const float* dW2     = (const float*)d_in[15];
    const float* db2     = (const float*)d_in[16];

    int N   = in_sizes[0] / 2;
    int E   = in_sizes[2];
    int OBS = E / 2;

    const int* src = ei;
    const int* dst = ei + E;

    float* out = (float*)d_out;
    float* z   = out + 2 * (size_t)OBS;

    float *r32, *bias2, *bias3, *biasd;
    __half *h1, *y16, *h2, *z16, *uv, *ws2, *ws3, *wsd;
    int *cursor;
    int2 *csr;
    cudaGetSymbolAddress((void**)&h1,      g_h1);
    cudaGetSymbolAddress((void**)&y16,     g_y16);
    cudaGetSymbolAddress((void**)&r32,     g_r32);
    cudaGetSymbolAddress((void**)&h2,      g_h2);
    cudaGetSymbolAddress((void**)&z16,     g_z16);
    cudaGetSymbolAddress((void**)&uv,      g_uv);
    cudaGetSymbolAddress((void**)&ws2,     g_ws2);
    cudaGetSymbolAddress((void**)&ws3,     g_ws3);
    cudaGetSymbolAddress((void**)&wsd,     g_wsd);
    cudaGetSymbolAddress((void**)&bias2,   g_bias2);
    cudaGetSymbolAddress((void**)&bias3,   g_bias3);
    cudaGetSymbolAddress((void**)&biasd,   g_biasd);
    cudaGetSymbolAddress((void**)&cursor,  g_cursor);
    cudaGetSymbolAddress((void**)&csr,     g_csr);

    // dyn smem: 2 H bufs + 2x2 W bufs + bias tile
    const int SMEM = 2 * (128 * 40) * 2 + 4 * (32 * 136) * 2 + 16 * 128 * 4;  // 63488
    cudaFuncSetAttribute(gemm_pipe<128, 128, 1>,
                         cudaFuncAttributeMaxDynamicSharedMemorySize, SMEM);
    cudaFuncSetAttribute(gemm_pipe<64, 128, 1>,
                         cudaFuncAttributeMaxDynamicSharedMemorySize, SMEM);
    cudaFuncSetAttribute(gemm_pipe<64, 256, 2>,
                         cudaFuncAttributeMaxDynamicSharedMemorySize, SMEM);

    const int TB = 256;
    int eb = (E + TB - 1) / TB;
    int mb128 = (N + 127) / 128;

    // ---- prep + cursor zero (1 launch) ----
    {
        int total = 128 * 128 + 64 * 128 + 64 * 256 + 128 + 128 + 256;
        int span = (N > total) ? N : total;
        prep_all<<<(span + TB - 1) / TB, TB>>>(W2_rel, W2_root, W3_rel, W3_root, dW1,
                                               b2, b3, db1, ws2, ws3, wsd,
                                               bias2, bias3, biasd, cursor, N);
    }

    // ---- Bucketed CSR ----
    fill_kernel<<<eb, TB>>>(src, dst, ew, cursor, csr, E);

    // ---- Layer 1 fused ----
    layer1_fused<<<(N * 4 + TB - 1) / TB, TB>>>(csr, cursor, x, W1_rel, W1_root, b1, h1, N);

    // ---- Layer 2: gemm (y fp16 | r fp32) + fused gather ----
    gemm_pipe<128, 128, 1><<<dim3(mb128, 1), 256, SMEM>>>(h1, ws2, bias2, y16, r32);
    gather64<<<(N + 31) / 32, TB>>>(csr, cursor, y16, r32, nullptr, h2, N, 1);

    // ---- Layer 3 ----
    gemm_pipe<64, 128, 1><<<dim3(mb128, 1), 256, SMEM>>>(h2, ws3, bias3, y16, r32);
    gather64<<<(N + 31) / 32, TB>>>(csr, cursor, y16, r32, z, z16, N, 0);

    // ---- Decoder ----
    gemm_pipe<64, 256, 2><<<dim3(mb128, 2), 256, SMEM>>>(z16, wsd, biasd, uv, nullptr);
    decode_edges_h<<<((size_t)OBS * 16 + TB - 1) / TB, TB>>>(src, dst, uv, dW2, db2, out, OBS);
}